// round 3
// baseline (speedup 1.0000x reference)
#include <cuda_runtime.h>
#include <math.h>

#define NQ   12
#define DIM  4096
#define NL   4
#define TPB  256

typedef unsigned long long ull;

// Packed-coefficient gate table, 8 float2 per (layer, wire):
//  c0=(u00r,u00r) c1=(-u00i,u00i) c2=(u01r,u01r) c3=(-u01i,u01i)
//  c4=(u10r,u10r) c5=(-u10i,u10i) c6=(u11r,u11r) c7=(-u11i,u11i)
__device__ float2 g_Up[NL * NQ * 8];

__global__ void precompute_gates(const float* __restrict__ qw) {
    int id = threadIdx.x;
    if (id >= NL * NQ) return;
    float a = qw[3 * id + 0];
    float b = qw[3 * id + 1];
    float g = qw[3 * id + 2];
    float cA = cosf(0.5f * a), sA = sinf(0.5f * a);
    float cB = cosf(0.5f * b), sB = sinf(0.5f * b);
    float cC = cosf(0.5f * g), sC = sinf(0.5f * g);
    float m00r =  cB * cA, m00i =  sB * sA;
    float m01r = -sB * cA, m01i = -cB * sA;
    float m10r =  sB * cA, m10i = -cB * sA;
    float m11r =  cB * cA, m11i = -sB * sA;
    // fused U = RZ * (RY*RX): row0 *= e^{-iC}, row1 *= e^{+iC}
    float u00r = cC * m00r + sC * m00i, u00i = cC * m00i - sC * m00r;
    float u01r = cC * m01r + sC * m01i, u01i = cC * m01i - sC * m01r;
    float u10r = cC * m10r - sC * m10i, u10i = cC * m10i + sC * m10r;
    float u11r = cC * m11r - sC * m11i, u11i = cC * m11i + sC * m11r;
    float2* o = &g_Up[id * 8];
    o[0] = make_float2( u00r, u00r);
    o[1] = make_float2(-u00i, u00i);
    o[2] = make_float2( u01r, u01r);
    o[3] = make_float2(-u01i, u01i);
    o[4] = make_float2( u10r, u10r);
    o[5] = make_float2(-u10i, u10i);
    o[6] = make_float2( u11r, u11r);
    o[7] = make_float2(-u11i, u11i);
}

// ---------------------------------------------------------------------------
// Packed f32x2 helpers (Blackwell sm_103a)
// ---------------------------------------------------------------------------
__device__ __forceinline__ ull sw2(ull v) {              // (x,y) -> (y,x)
    unsigned lo, hi;
    asm("mov.b64 {%0,%1}, %2;" : "=r"(lo), "=r"(hi) : "l"(v));
    ull o;
    asm("mov.b64 %0, {%1,%2};" : "=l"(o) : "r"(hi), "r"(lo));
    return o;
}
__device__ __forceinline__ ull mul2(ull a, ull b) {
    ull d;
    asm("mul.rn.f32x2 %0, %1, %2;" : "=l"(d) : "l"(a), "l"(b));
    return d;
}
__device__ __forceinline__ ull fma2(ull a, ull b, ull c) {
    ull d;
    asm("fma.rn.f32x2 %0, %1, %2, %3;" : "=l"(d) : "l"(a), "l"(b), "l"(c));
    return d;
}

__device__ __forceinline__ int physHIGH(int x) {
    return ((x & 0xFF) << 4) | (((x >> 8) ^ x) & 15);
}

// Apply fused 1q gate on register-slot bit bb with packed coefficients cg[8]
#define APPLY_GATE_P(bb, cg) do {                                            \
    const ull d00 = (cg)[0], e00 = (cg)[1], d01 = (cg)[2], e01 = (cg)[3];    \
    const ull d10 = (cg)[4], e10 = (cg)[5], d11 = (cg)[6], e11 = (cg)[7];    \
    _Pragma("unroll")                                                        \
    for (int m = 0; m < 8; m++) {                                            \
        const int lowm = (1 << (bb)) - 1;                                    \
        const int i0 = ((m & ~lowm) << 1) | (m & lowm);                      \
        const int i1 = i0 | (1 << (bb));                                     \
        ull v0 = r[i0], v1 = r[i1];                                          \
        ull v0s = sw2(v0), v1s = sw2(v1);                                    \
        ull n0 = mul2(d00, v0);                                              \
        n0 = fma2(e00, v0s, n0);                                             \
        n0 = fma2(d01, v1, n0);                                              \
        n0 = fma2(e01, v1s, n0);                                             \
        ull n1 = mul2(d10, v0);                                              \
        n1 = fma2(e10, v0s, n1);                                             \
        n1 = fma2(d11, v1, n1);                                              \
        n1 = fma2(e11, v1s, n1);                                             \
        r[i0] = n0; r[i1] = n1;                                              \
    }                                                                        \
} while (0)

__global__ __launch_bounds__(TPB, 2) void qsim(const float* __restrict__ x,
                                               const float* __restrict__ dw,
                                               const float* __restrict__ db,
                                               float* __restrict__ out) {
    __shared__ float2 s_psi[DIM];            // 32 KB state (swizzled layouts)
    __shared__ float2 s_Up[NL * NQ * 8];     // packed gate coefficients (3 KB)
    __shared__ float  s_x[NQ];
    __shared__ float  s_c[NQ], s_s[NQ];      // encoding cos/sin by BIT POSITION
    __shared__ float  s_scalar[2];
    __shared__ float  s_red[8 * NQ];
    __shared__ float  s_q[NQ];

    ull* s64 = reinterpret_cast<ull*>(s_psi);
    const ull* cU = reinterpret_cast<const ull*>(s_Up);

    const int t = threadIdx.x;
    const int bidx = blockIdx.x;

    for (int i = t; i < NL * NQ * 8; i += TPB) s_Up[i] = g_Up[i];
    if (t < NQ) s_x[t] = x[bidx * NQ + t];
    __syncthreads();

    if (t == 0) {
        float ss = 0.f, ma = 0.f;
        #pragma unroll
        for (int w = 0; w < NQ; w++) {
            float v = s_x[w];
            ss += v * v;
            ma = fmaxf(ma, fabsf(v));
        }
        float rr = rsqrtf(fmaxf(ss, 1e-12f));
        s_scalar[0] = rr;
        s_scalar[1] = ma * rr;
    }
    __syncthreads();
    if (t < NQ) {
        float rr = s_scalar[0], m = s_scalar[1];
        float ang = 3.14159265358979f * (s_x[t] * rr) / (m + 1e-8f);
        int p = 11 - t;                      // wire t at bit position 11-t
        s_c[p] = cosf(0.5f * ang);
        s_s[p] = sinf(0.5f * ang);
    }
    __syncthreads();

    ull r[16];                               // 16 packed complex amps / thread
    const int storeBase = (t << 4) | (t & 15);     // store: addr = storeBase ^ s

    #pragma unroll 1
    for (int layer = 0; layer < NL; layer++) {
        // ---------- pass MID: active positions {4..7}
        if (layer == 0) {
            // product-state init from RY encoding (imag = 0)
            float ct = 1.f;
            #pragma unroll
            for (int p = 0; p < 4; p++)  ct *= ((t >> p) & 1) ? s_s[p] : s_c[p];
            #pragma unroll
            for (int p = 8; p < 12; p++) ct *= ((t >> (p - 4)) & 1) ? s_s[p] : s_c[p];
            #pragma unroll
            for (int s = 0; s < 16; s++) {
                float ms = 1.f;
                #pragma unroll
                for (int p = 4; p < 8; p++) ms *= ((s >> (p - 4)) & 1) ? s_s[p] : s_c[p];
                r[s] = (ull)__float_as_uint(ct * ms);    // hi (imag) = 0
            }
        } else {
            // load from HIGH layout with CNOT-ring perm folded in
            int T  = ((t & 0xF0) << 4) | (t & 15);
            int Xt = T ^ (T >> 1) ^ ((t & 1) ? 0xC00 : 0);
            int base = physHIGH(Xt & 0xFFF);
            #pragma unroll
            for (int s = 0; s < 16; s++) {
                int Xs = ((s << 4) ^ (s << 3)) & 0xFFF;
                r[s] = s64[base ^ physHIGH(Xs)];
            }
        }
        APPLY_GATE_P(0, &cU[(layer * NQ + 7) * 8]);   // position 4 = wire 7
        APPLY_GATE_P(1, &cU[(layer * NQ + 6) * 8]);
        APPLY_GATE_P(2, &cU[(layer * NQ + 5) * 8]);
        APPLY_GATE_P(3, &cU[(layer * NQ + 4) * 8]);
        if (layer > 0) __syncthreads();               // loads done before clobber
        #pragma unroll
        for (int s = 0; s < 16; s++) s64[storeBase ^ s] = r[s];
        __syncthreads();

        // ---------- pass LOW: active {0..3}; load from MID layout
        {
            int base = ((t & 0xF0) << 4) | (t & 15);
            #pragma unroll
            for (int s = 0; s < 16; s++) r[s] = s64[base ^ ((s << 4) | s)];
        }
        APPLY_GATE_P(0, &cU[(layer * NQ + 11) * 8]);  // position 0 = wire 11
        APPLY_GATE_P(1, &cU[(layer * NQ + 10) * 8]);
        APPLY_GATE_P(2, &cU[(layer * NQ +  9) * 8]);
        APPLY_GATE_P(3, &cU[(layer * NQ +  8) * 8]);
        __syncthreads();
        #pragma unroll
        for (int s = 0; s < 16; s++) s64[storeBase ^ s] = r[s];
        __syncthreads();

        // ---------- pass HIGH: active {8..11}; load from LOW layout
        {
            int base = t ^ ((t >> 4) & 15);
            #pragma unroll
            for (int s = 0; s < 16; s++) r[s] = s64[base ^ (s << 8)];
        }
        APPLY_GATE_P(0, &cU[(layer * NQ + 3) * 8]);   // position 8 = wire 3
        APPLY_GATE_P(1, &cU[(layer * NQ + 2) * 8]);
        APPLY_GATE_P(2, &cU[(layer * NQ + 1) * 8]);
        APPLY_GATE_P(3, &cU[(layer * NQ + 0) * 8]);
        if (layer < NL - 1) {
            __syncthreads();
            #pragma unroll
            for (int s = 0; s < 16; s++) s64[storeBase ^ s] = r[s];
            __syncthreads();
        }
        // layer-boundary CNOT ring folds into next MID load / epilogue map
    }

    // ---------- epilogue: final CNOT perm via inverse index map, then <Z_w>
    // r holds HIGH ownership: logical (pre-final-perm) L = (s<<8) | t
    int xt = t ^ ((__popc(t) & 1) ? 0xC00 : 0);
    xt ^= xt >> 1; xt ^= xt >> 2; xt ^= xt >> 4; xt ^= xt >> 8;

    float z[NQ];
    #pragma unroll
    for (int w = 0; w < NQ; w++) z[w] = 0.f;
    #pragma unroll
    for (int s = 0; s < 16; s++) {
        int xs = (s << 8) ^ ((__popc(s) & 1) ? 0xC00 : 0);
        xs ^= xs >> 1; xs ^= xs >> 2; xs ^= xs >> 4; xs ^= xs >> 8;
        int j = xt ^ xs;                      // final logical basis index
        float vx = __uint_as_float((unsigned)(r[s] & 0xFFFFFFFFull));
        float vy = __uint_as_float((unsigned)(r[s] >> 32));
        float pr = vx * vx + vy * vy;
        #pragma unroll
        for (int w = 0; w < NQ; w++)
            z[w] += ((j >> (11 - w)) & 1) ? -pr : pr;
    }

    const int lane = t & 31, warp = t >> 5;
    #pragma unroll
    for (int w = 0; w < NQ; w++) {
        float v = z[w];
        #pragma unroll
        for (int off = 16; off; off >>= 1)
            v += __shfl_down_sync(0xffffffffu, v, off);
        if (lane == 0) s_red[warp * NQ + w] = v;
    }
    __syncthreads();
    if (t < NQ) {
        float qv = 0.f;
        #pragma unroll
        for (int wp = 0; wp < 8; wp++) qv += s_red[wp * NQ + t];
        s_q[t] = qv;
    }
    __syncthreads();
    if (t < NQ) {
        float acc = db[t];
        #pragma unroll
        for (int w = 0; w < NQ; w++) acc += s_q[w] * dw[w * NQ + t];
        out[bidx * NQ + t] = tanhf(acc);
    }
}

extern "C" void kernel_launch(void* const* d_in, const int* in_sizes, int n_in,
                              void* d_out, int out_size) {
    const float* x  = (const float*)d_in[0];
    const float* qw = (const float*)d_in[1];
    const float* dw = (const float*)d_in[2];
    const float* db = (const float*)d_in[3];
    float* out = (float*)d_out;

    int batch = in_sizes[0] / NQ;

    precompute_gates<<<1, 64>>>(qw);
    qsim<<<batch, TPB>>>(x, dw, db, out);
}